// round 8
// baseline (speedup 1.0000x reference)
#include <cuda_runtime.h>
#include <cuda_fp16.h>
#include <math.h>
#include <float.h>
#include <stdint.h>

// Problem constants: B=64, S=512, D=128, K=1024; N = B*S
#define N_TOK 32768
#define DIM   128
#define KCODE 1024
#define QBLK  8
#define NQB   (N_TOK / QBLK)

#define BN        64            // codes per smem chunk
#define QCODES    256           // codes per tile (quarter codebook)
#define NCPT      (QCODES / BN) // chunks per tile = 4
#define NTILES    2048          // (32768/64 row-blocks) * 4 quarters
#define NWT       2048          // warp-tiles of 16 rows
#define GRID_ARG  444           // 148 SMs * 3 CTAs -> one clean wave

#define EPAD      136           // halves per padded e-row (272 B)
#define ROW_B     (EPAD * 2)    // 272
#define CHUNK_B   (BN * ROW_B)  // 17408 bytes per split per chunk
#define CHUNK_U4  (CHUNK_B / 16)
#define BUF_B     (2 * CHUNK_B) // hi+lo = 34816
#define SMEM_TOT  (2 * BUF_B)   // double buffer = 69632

// Scratch (no allocations allowed)
__device__ unsigned long long g_pack[N_TOK];   // packed (dist,idx), merged via atomicMin
__device__ float  g_enorm[KCODE];
__device__ float  g_zn[N_TOK];
__device__ int    g_counts[KCODE];
__device__ double g_losspart[NQB];
__device__ unsigned int g_tilectr;
__device__ __half g_ehi[KCODE * EPAD];         // e * 1024, fp16 hi, padded rows
__device__ __half g_elo[KCODE * EPAD];         // residual lo
__device__ uint4  g_afrag[NWT * 16 * 32];      // pre-split z fragments, coalesced layout

// ------------------------------------------------------------ helpers
__device__ __forceinline__ uint32_t smem_u32(const void* p) {
    uint32_t a;
    asm("{ .reg .u64 t; cvta.to.shared.u64 t, %1; cvt.u32.u64 %0, t; }" : "=r"(a) : "l"(p));
    return a;
}
__device__ __forceinline__ void cpasync16(uint32_t dst, const void* src) {
    asm volatile("{\n\t.reg .u64 gp;\n\tcvta.to.global.u64 gp, %1;\n\t"
                 "cp.async.cg.shared.global [%0], [gp], 16;\n\t}"
                 :: "r"(dst), "l"(src));
}
#define CP_COMMIT() asm volatile("cp.async.commit_group;" ::: "memory")
#define CP_WAIT0()  asm volatile("cp.async.wait_group 0;" ::: "memory")

__device__ __forceinline__ void ldmatrix_x4(uint32_t& r0, uint32_t& r1,
                                            uint32_t& r2, uint32_t& r3, uint32_t addr) {
    asm volatile("ldmatrix.sync.aligned.m8n8.x4.shared.b16 {%0,%1,%2,%3}, [%4];"
                 : "=r"(r0), "=r"(r1), "=r"(r2), "=r"(r3) : "r"(addr));
}
// m16n8k16 row.col f32.f16.f16.f32
__device__ __forceinline__ void mma16816(float* c, const uint32_t* a,
                                         uint32_t b0, uint32_t b1) {
    asm volatile("mma.sync.aligned.m16n8k16.row.col.f32.f16.f16.f32 "
                 "{%0,%1,%2,%3}, {%4,%5,%6,%7}, {%8,%9}, {%0,%1,%2,%3};"
                 : "+f"(c[0]), "+f"(c[1]), "+f"(c[2]), "+f"(c[3])
                 : "r"(a[0]), "r"(a[1]), "r"(a[2]), "r"(a[3]), "r"(b0), "r"(b1));
}
__device__ __forceinline__ void split2(float2 v, uint32_t& h, uint32_t& l) {
    __half hx = __float2half_rn(v.x), hy = __float2half_rn(v.y);
    __half lx = __float2half_rn(v.x - __half2float(hx));
    __half ly = __float2half_rn(v.y - __half2float(hy));
    h = ((uint32_t)__half_as_ushort(hy) << 16) | __half_as_ushort(hx);
    l = ((uint32_t)__half_as_ushort(ly) << 16) | __half_as_ushort(lx);
}
// monotone float -> uint map; pack (value, index): min pack == (min val, first idx)
__device__ __forceinline__ unsigned long long pack_vi(float v, int idx) {
    uint32_t u = __float_as_uint(v);
    u = (u & 0x80000000u) ? ~u : (u | 0x80000000u);
    return ((unsigned long long)u << 32) | (uint32_t)idx;
}

// ---------------------------------------------------------------- init
__global__ void init_kernel() {
    int i = blockIdx.x * blockDim.x + threadIdx.x;
    if (i < KCODE) g_counts[i] = 0;
    if (i == 0) g_tilectr = 0;
    for (int r = i; r < N_TOK; r += gridDim.x * blockDim.x)
        g_pack[r] = 0xFFFFFFFFFFFFFFFFull;
}

// ---------------------------------------------------------------- ||e||^2 (reference order)
__global__ void enorm_kernel(const float* __restrict__ emb) {
    int k = blockIdx.x * blockDim.x + threadIdx.x;
    if (k >= KCODE) return;
    const float* e = emb + (size_t)k * DIM;
    float s = 0.f;
    for (int d = 0; d < DIM; d++) {
        float v = e[d];
        s = __fadd_rn(s, __fmul_rn(v, v));
    }
    g_enorm[k] = s;
}

// ---------------------------------------------------------------- e -> (e*1024) fp16 hi/lo
__global__ void prep_e(const float* __restrict__ emb) {
    int idx = blockIdx.x * blockDim.x + threadIdx.x;
    if (idx >= KCODE * DIM) return;
    int k = idx >> 7, d = idx & 127;
    float v = emb[idx] * 1024.0f;                 // exact scaling
    __half h = __float2half_rn(v);
    __half l = __float2half_rn(v - __half2float(h));
    g_ehi[k * EPAD + d] = h;
    g_elo[k * EPAD + d] = l;
}

// ---------------------------------------------------------------- z -> fragments + norms
// One warp per 16-row warp-tile; emits A fragments (hi 32 regs + lo 32 regs per lane)
// in a [wt][r4][lane] uint4 layout so argmin's reload is 16 coalesced LDG.128.
__global__ void prep_z(const float* __restrict__ z) {
    const int tid = threadIdx.x, wid = tid >> 5, lane = tid & 31;
    const int wt = blockIdx.x * 4 + wid;
    const int g = lane >> 2, cc = lane & 3;
    const int rA = wt * 16 + g, rB = rA + 8;

    uint32_t ahi[32], alo[32];
    #pragma unroll
    for (int ks = 0; ks < 8; ks++) {
        float2 a0 = *(const float2*)(z + (size_t)rA * DIM + ks * 16 + 2 * cc);
        float2 a1 = *(const float2*)(z + (size_t)rB * DIM + ks * 16 + 2 * cc);
        float2 a2 = *(const float2*)(z + (size_t)rA * DIM + ks * 16 + 2 * cc + 8);
        float2 a3 = *(const float2*)(z + (size_t)rB * DIM + ks * 16 + 2 * cc + 8);
        split2(a0, ahi[ks * 4 + 0], alo[ks * 4 + 0]);
        split2(a1, ahi[ks * 4 + 1], alo[ks * 4 + 1]);
        split2(a2, ahi[ks * 4 + 2], alo[ks * 4 + 2]);
        split2(a3, ahi[ks * 4 + 3], alo[ks * 4 + 3]);
    }
    #pragma unroll
    for (int r4 = 0; r4 < 8; r4++) {
        g_afrag[((size_t)wt * 16 + r4) * 32 + lane] =
            make_uint4(ahi[r4*4], ahi[r4*4+1], ahi[r4*4+2], ahi[r4*4+3]);
        g_afrag[((size_t)wt * 16 + 8 + r4) * 32 + lane] =
            make_uint4(alo[r4*4], alo[r4*4+1], alo[r4*4+2], alo[r4*4+3]);
    }
    // per-row ||z||^2, sequential fp32 mul-then-add (reference rounding)
    if (lane < 16) {
        const float* zr = z + (size_t)(wt * 16 + lane) * DIM;
        float s = 0.f;
        for (int d = 0; d < DIM; d++)
            s = __fadd_rn(s, __fmul_rn(zr[d], zr[d]));
        g_zn[wt * 16 + lane] = s;
    }
}

// ---------------------------------------------------------------- argmin: persistent, work-stolen
// Tile = 64 rows x 256 codes. 2048 tiles, 444 CTAs (one wave at 3/SM).
// dot = zhi*ehi + zhi*elo + zlo*ehi (fp32 accum, chained into one C — full rate).
extern __shared__ char asm_smem[];

__global__ __launch_bounds__(128, 3) void argmin_mma() {
    __shared__ int s_tile;
    char* smem = asm_smem;
    const uint32_t sbase = smem_u32(smem);
    const int tid = threadIdx.x, wid = tid >> 5, lane = tid & 31;
    const int g = lane >> 2, cc = lane & 3;

    // ldmatrix per-lane row map: lanes 0-7 -> bh k0..7, 8-15 -> bh k8..15,
    // 16-23 -> bl k0..7, 24-31 -> bl k8..15 (matrix row = code n)
    const int sel = lane >> 3, r8 = lane & 7;
    const uint32_t laneoff = (uint32_t)((sel >> 1) * CHUNK_B + (sel & 1) * 16 + r8 * ROW_B);

    for (;;) {
        if (tid == 0) s_tile = (int)atomicAdd(&g_tilectr, 1u);
        __syncthreads();
        const int t = s_tile;
        if (t >= NTILES) break;
        const int rb = t >> 2;            // 64-row block
        const int code_base = (t & 3) * QCODES;
        const int wt = rb * 4 + wid;
        const int rA = wt * 16 + g, rB = rA + 8;

        // chunk 0 prefetch first (longest latency), then A fragments under it
        {
            uint32_t dst = sbase;
            const char* hs = (const char*)(g_ehi + (size_t)code_base * EPAD);
            const char* ls = (const char*)(g_elo + (size_t)code_base * EPAD);
            for (int i = tid; i < CHUNK_U4; i += 128) {
                cpasync16(dst + i * 16,           hs + i * 16);
                cpasync16(dst + CHUNK_B + i * 16, ls + i * 16);
            }
            CP_COMMIT();
        }

        uint32_t ahi[32], alo[32];
        #pragma unroll
        for (int r4 = 0; r4 < 8; r4++) {
            uint4 vh = g_afrag[((size_t)wt * 16 + r4) * 32 + lane];
            ahi[r4*4] = vh.x; ahi[r4*4+1] = vh.y; ahi[r4*4+2] = vh.z; ahi[r4*4+3] = vh.w;
            uint4 vl = g_afrag[((size_t)wt * 16 + 8 + r4) * 32 + lane];
            alo[r4*4] = vl.x; alo[r4*4+1] = vl.y; alo[r4*4+2] = vl.z; alo[r4*4+3] = vl.w;
        }
        const float znA = g_zn[rA];
        const float znB = g_zn[rB];

        CP_WAIT0();
        __syncthreads();

        float minvA = FLT_MAX, minvB = FLT_MAX;
        int   miniA = 0, miniB = 0;

        for (int c = 0; c < NCPT; c++) {
            if (c + 1 < NCPT) {
                uint32_t dst = sbase + ((c + 1) & 1) * BUF_B;
                const char* hs = (const char*)(g_ehi + (size_t)(code_base + (c + 1) * BN) * EPAD);
                const char* ls = (const char*)(g_elo + (size_t)(code_base + (c + 1) * BN) * EPAD);
                for (int i = tid; i < CHUNK_U4; i += 128) {
                    cpasync16(dst + i * 16,           hs + i * 16);
                    cpasync16(dst + CHUNK_B + i * 16, ls + i * 16);
                }
                CP_COMMIT();
            }

            const uint32_t bbase = sbase + (c & 1) * BUF_B + laneoff;
            const int cbase = code_base + c * BN;

            #pragma unroll
            for (int g2 = 0; g2 < 2; g2++) {
                float acc[4][4];
                #pragma unroll
                for (int q = 0; q < 4; q++)
                    #pragma unroll
                    for (int w = 0; w < 4; w++) acc[q][w] = 0.f;

                #pragma unroll
                for (int ks = 0; ks < 8; ks++) {
                    #pragma unroll
                    for (int ntl = 0; ntl < 4; ntl++) {
                        uint32_t b0, b1, b2, b3;
                        ldmatrix_x4(b0, b1, b2, b3,
                                    bbase + (g2 * 4 + ntl) * (8 * ROW_B) + ks * 32);
                        mma16816(acc[ntl], &ahi[ks * 4], b0, b1);   // hi*hi
                        mma16816(acc[ntl], &ahi[ks * 4], b2, b3);   // hi*lo
                        mma16816(acc[ntl], &alo[ks * 4], b0, b1);   // lo*hi
                    }
                }

                // q = (zn + en) + dot * (-2^-9)  [exact unscale, same rounding]
                float qA[8], qB[8];
                #pragma unroll
                for (int ntl = 0; ntl < 4; ntl++) {
                    int code0 = cbase + (g2 * 4 + ntl) * 8 + 2 * cc;
                    float2 en2 = *(const float2*)(g_enorm + code0);
                    qA[2*ntl]   = __fadd_rn(__fadd_rn(znA, en2.x), acc[ntl][0] * -0.001953125f);
                    qA[2*ntl+1] = __fadd_rn(__fadd_rn(znA, en2.y), acc[ntl][1] * -0.001953125f);
                    qB[2*ntl]   = __fadd_rn(__fadd_rn(znB, en2.x), acc[ntl][2] * -0.001953125f);
                    qB[2*ntl+1] = __fadd_rn(__fadd_rn(znB, en2.y), acc[ntl][3] * -0.001953125f);
                }
                float cmA = fminf(fminf(fminf(qA[0], qA[1]), fminf(qA[2], qA[3])),
                                  fminf(fminf(qA[4], qA[5]), fminf(qA[6], qA[7])));
                if (cmA < minvA) {
                    minvA = cmA;
                    #pragma unroll
                    for (int q = 7; q >= 0; q--)
                        if (qA[q] == cmA)
                            miniA = cbase + g2 * 32 + (q >> 1) * 8 + 2 * cc + (q & 1);
                }
                float cmB = fminf(fminf(fminf(qB[0], qB[1]), fminf(qB[2], qB[3])),
                                  fminf(fminf(qB[4], qB[5]), fminf(qB[6], qB[7])));
                if (cmB < minvB) {
                    minvB = cmB;
                    #pragma unroll
                    for (int q = 7; q >= 0; q--)
                        if (qB[q] == cmB)
                            miniB = cbase + g2 * 32 + (q >> 1) * 8 + 2 * cc + (q & 1);
                }
            }

            if (c + 1 < NCPT) CP_WAIT0();
            __syncthreads();
        }

        // lexicographic reduce across 4 lanes per row, then global atomicMin merge
        #pragma unroll
        for (int o = 1; o <= 2; o <<= 1) {
            float vA = __shfl_xor_sync(0xffffffffu, minvA, o);
            int   iA = __shfl_xor_sync(0xffffffffu, miniA, o);
            if (vA < minvA || (vA == minvA && iA < miniA)) { minvA = vA; miniA = iA; }
            float vB = __shfl_xor_sync(0xffffffffu, minvB, o);
            int   iB = __shfl_xor_sync(0xffffffffu, miniB, o);
            if (vB < minvB || (vB == minvB && iB < miniB)) { minvB = vB; miniB = iB; }
        }
        if (cc == 0) {
            atomicMin(&g_pack[rA], pack_vi(minvA, miniA));
            atomicMin(&g_pack[rB], pack_vi(minvB, miniB));
        }
    }
}

// ---------------------------------------------------------------- gather + loss + hist
__global__ void quantize_kernel(const float* __restrict__ z,
                                const float* __restrict__ emb,
                                const unsigned char* __restrict__ mask,
                                float* __restrict__ out) {
    const int warp = threadIdx.x >> 5;
    const int lane = threadIdx.x & 31;
    const int row  = blockIdx.x * QBLK + warp;
    const int code = (int)(g_pack[row] & 0xffffffffu);

    const float4 zv = *(const float4*)(z   + (size_t)row  * DIM + lane * 4);
    const float4 ev = *(const float4*)(emb + (size_t)code * DIM + lane * 4);

    float dx = __fadd_rn(ev.x, -zv.x);
    float dy = __fadd_rn(ev.y, -zv.y);
    float dz = __fadd_rn(ev.z, -zv.z);
    float dw = __fadd_rn(ev.w, -zv.w);

    float4 o;
    o.x = __fadd_rn(zv.x, dx);
    o.y = __fadd_rn(zv.y, dy);
    o.z = __fadd_rn(zv.z, dz);
    o.w = __fadd_rn(zv.w, dw);
    *(float4*)(out + (size_t)row * DIM + lane * 4) = o;

    float ss = dx * dx + dy * dy + dz * dz + dw * dw;
    #pragma unroll
    for (int off = 16; off; off >>= 1) ss += __shfl_xor_sync(0xffffffffu, ss, off);

    __shared__ float sps[QBLK];
    if (lane == 0) {
        sps[warp] = ss;
        if (!mask[row]) atomicAdd(&g_counts[code], 1);
    }
    __syncthreads();
    if (threadIdx.x == 0) {
        double b = 0.0;
        #pragma unroll
        for (int w = 0; w < QBLK; w++) b += (double)sps[w];
        g_losspart[blockIdx.x] = b;
    }
}

// ---------------------------------------------------------------- scalars
__global__ void finalize_kernel(const unsigned char* __restrict__ mask,
                                float* __restrict__ out, long long out_size) {
    __shared__ double dred[1024];
    __shared__ int    ired[1024];
    __shared__ float  fred[1024];
    const int k = threadIdx.x;

    int vsum = 0;
    {
        const uchar4* m4 = (const uchar4*)mask;
        #pragma unroll
        for (int i = 0; i < (N_TOK / 4) / 1024; i++) {
            uchar4 m = m4[k + i * 1024];
            vsum += (m.x ? 0 : 1) + (m.y ? 0 : 1) + (m.z ? 0 : 1) + (m.w ? 0 : 1);
        }
    }
    double lsum = 0.0;
    #pragma unroll
    for (int i = 0; i < NQB / 1024; i++) lsum += g_losspart[k + i * 1024];
    dred[k] = lsum;
    ired[k] = vsum;
    __syncthreads();
    for (int s = 512; s > 0; s >>= 1) {
        if (k < s) { dred[k] += dred[k + s]; ired[k] += ired[k + s]; }
        __syncthreads();
    }
    const float valid = (float)ired[0];
    const double losssum = dred[0];

    float p = __fdiv_rn((float)g_counts[k], valid);
    fred[k] = __fmul_rn(p, logf(__fadd_rn(p, 1e-10f)));
    __syncthreads();
    for (int s = 512; s > 0; s >>= 1) {
        if (k < s) fred[k] += fred[k + s];
        __syncthreads();
    }
    if (k == 0 && out_size >= (long long)N_TOK * DIM + 2) {
        double mean = losssum / (double)((long long)N_TOK * DIM);
        float v = (float)mean;
        out[(long long)N_TOK * DIM]     = __fadd_rn(v, __fmul_rn(0.25f, v));
        out[(long long)N_TOK * DIM + 1] = expf(-fred[0]);
    }
}

// ---------------------------------------------------------------- launch
extern "C" void kernel_launch(void* const* d_in, const int* in_sizes, int n_in,
                              void* d_out, int out_size) {
    const float* z = nullptr;
    const float* emb = nullptr;
    const unsigned char* mask = nullptr;
    for (int i = 0; i < n_in; i++) {
        if      (in_sizes[i] == N_TOK * DIM) z    = (const float*)d_in[i];
        else if (in_sizes[i] == KCODE * DIM) emb  = (const float*)d_in[i];
        else if (in_sizes[i] == N_TOK)       mask = (const unsigned char*)d_in[i];
    }
    float* out = (float*)d_out;

    cudaFuncSetAttribute(argmin_mma, cudaFuncAttributeMaxDynamicSharedMemorySize, SMEM_TOT);

    init_kernel    <<<34, 1024>>>();
    enorm_kernel   <<<4, 256>>>(emb);
    prep_e         <<<(KCODE * DIM) / 256, 256>>>(emb);
    prep_z         <<<NWT / 4, 128>>>(z);
    argmin_mma     <<<GRID_ARG, 128, SMEM_TOT>>>();
    quantize_kernel<<<NQB, QBLK * 32>>>(z, emb, mask, out);
    finalize_kernel<<<1, 1024>>>(mask, out, (long long)out_size);
}

// round 9
// speedup vs baseline: 1.0112x; 1.0112x over previous
#include <cuda_runtime.h>
#include <cuda_fp16.h>
#include <math.h>
#include <float.h>
#include <stdint.h>

// Problem constants: B=64, S=512, D=128, K=1024; N = B*S
#define N_TOK 32768
#define DIM   128
#define KCODE 1024
#define QBLK  8
#define NQB   (N_TOK / QBLK)

#define BN        64            // codes per smem chunk
#define QCODES    256           // codes per tile (quarter codebook)
#define NCPT      (QCODES / BN) // chunks per tile = 4
#define NTILES    2048          // (32768/64 row-blocks) * 4 quarters
#define NWT       2048          // warp-tiles of 16 rows
#define GRID_ARG  444           // 148 SMs * 3 CTAs -> one clean wave

#define EPAD      136           // halves per padded e-row (272 B)
#define ROW_B     (EPAD * 2)    // 272
#define CHUNK_B   (BN * ROW_B)  // 17408 bytes per split per chunk
#define CHUNK_U4  (CHUNK_B / 16)
#define BUF_B     (2 * CHUNK_B) // hi+lo = 34816
#define SMEM_TOT  (2 * BUF_B)   // double buffer = 69632

// Scratch (no allocations allowed)
__device__ unsigned long long g_pack[N_TOK];   // packed (dist,idx), merged via atomicMin
__device__ float  g_enorm[KCODE];
__device__ float  g_zn[N_TOK];
__device__ int    g_counts[KCODE];
__device__ double g_losspart[NQB];
__device__ unsigned int g_tilectr;
__device__ __half g_ehi[KCODE * EPAD];         // e * 1024, fp16 hi, padded rows
__device__ __half g_elo[KCODE * EPAD];         // residual lo
__device__ uint4  g_afrag[NWT * 16 * 32];      // pre-split z fragments, coalesced layout

// ------------------------------------------------------------ helpers
__device__ __forceinline__ uint32_t smem_u32(const void* p) {
    uint32_t a;
    asm("{ .reg .u64 t; cvta.to.shared.u64 t, %1; cvt.u32.u64 %0, t; }" : "=r"(a) : "l"(p));
    return a;
}
__device__ __forceinline__ void cpasync16(uint32_t dst, const void* src) {
    asm volatile("{\n\t.reg .u64 gp;\n\tcvta.to.global.u64 gp, %1;\n\t"
                 "cp.async.cg.shared.global [%0], [gp], 16;\n\t}"
                 :: "r"(dst), "l"(src));
}
#define CP_COMMIT() asm volatile("cp.async.commit_group;" ::: "memory")
#define CP_WAIT0()  asm volatile("cp.async.wait_group 0;" ::: "memory")

__device__ __forceinline__ void ldmatrix_x4(uint32_t& r0, uint32_t& r1,
                                            uint32_t& r2, uint32_t& r3, uint32_t addr) {
    asm volatile("ldmatrix.sync.aligned.m8n8.x4.shared.b16 {%0,%1,%2,%3}, [%4];"
                 : "=r"(r0), "=r"(r1), "=r"(r2), "=r"(r3) : "r"(addr));
}
// m16n8k16 row.col f32.f16.f16.f32
__device__ __forceinline__ void mma16816(float* c, const uint32_t* a,
                                         uint32_t b0, uint32_t b1) {
    asm volatile("mma.sync.aligned.m16n8k16.row.col.f32.f16.f16.f32 "
                 "{%0,%1,%2,%3}, {%4,%5,%6,%7}, {%8,%9}, {%0,%1,%2,%3};"
                 : "+f"(c[0]), "+f"(c[1]), "+f"(c[2]), "+f"(c[3])
                 : "r"(a[0]), "r"(a[1]), "r"(a[2]), "r"(a[3]), "r"(b0), "r"(b1));
}
__device__ __forceinline__ void split2(float2 v, uint32_t& h, uint32_t& l) {
    __half hx = __float2half_rn(v.x), hy = __float2half_rn(v.y);
    __half lx = __float2half_rn(v.x - __half2float(hx));
    __half ly = __float2half_rn(v.y - __half2float(hy));
    h = ((uint32_t)__half_as_ushort(hy) << 16) | __half_as_ushort(hx);
    l = ((uint32_t)__half_as_ushort(ly) << 16) | __half_as_ushort(lx);
}
// monotone float -> uint map; pack (value, index): min pack == (min val, first idx)
__device__ __forceinline__ unsigned long long pack_vi(float v, int idx) {
    uint32_t u = __float_as_uint(v);
    u = (u & 0x80000000u) ? ~u : (u | 0x80000000u);
    return ((unsigned long long)u << 32) | (uint32_t)idx;
}

// ---------------------------------------------------------------- init
__global__ void init_kernel() {
    int i = blockIdx.x * blockDim.x + threadIdx.x;
    if (i < KCODE) g_counts[i] = 0;
    if (i == 0) g_tilectr = 0;
    for (int r = i; r < N_TOK; r += gridDim.x * blockDim.x)
        g_pack[r] = 0xFFFFFFFFFFFFFFFFull;
}

// ---------------------------------------------------------------- ||e||^2 (reference order)
__global__ void enorm_kernel(const float* __restrict__ emb) {
    int k = blockIdx.x * blockDim.x + threadIdx.x;
    if (k >= KCODE) return;
    const float* e = emb + (size_t)k * DIM;
    float s = 0.f;
    for (int d = 0; d < DIM; d++) {
        float v = e[d];
        s = __fadd_rn(s, __fmul_rn(v, v));
    }
    g_enorm[k] = s;
}

// ---------------------------------------------------------------- e -> (e*1024) fp16 hi/lo
__global__ void prep_e(const float* __restrict__ emb) {
    int idx = blockIdx.x * blockDim.x + threadIdx.x;
    if (idx >= KCODE * DIM) return;
    int k = idx >> 7, d = idx & 127;
    float v = emb[idx] * 1024.0f;                 // exact scaling
    __half h = __float2half_rn(v);
    __half l = __float2half_rn(v - __half2float(h));
    g_ehi[k * EPAD + d] = h;
    g_elo[k * EPAD + d] = l;
}

// ---------------------------------------------------------------- z -> fragments + norms
// One warp per 16-row warp-tile; emits A fragments (hi 32 regs + lo 32 regs per lane)
// in a [wt][r4][lane] uint4 layout so argmin's reload is 16 coalesced LDG.128.
__global__ void prep_z(const float* __restrict__ z) {
    const int tid = threadIdx.x, wid = tid >> 5, lane = tid & 31;
    const int wt = blockIdx.x * 4 + wid;
    const int g = lane >> 2, cc = lane & 3;
    const int rA = wt * 16 + g, rB = rA + 8;

    uint32_t ahi[32], alo[32];
    #pragma unroll
    for (int ks = 0; ks < 8; ks++) {
        float2 a0 = *(const float2*)(z + (size_t)rA * DIM + ks * 16 + 2 * cc);
        float2 a1 = *(const float2*)(z + (size_t)rB * DIM + ks * 16 + 2 * cc);
        float2 a2 = *(const float2*)(z + (size_t)rA * DIM + ks * 16 + 2 * cc + 8);
        float2 a3 = *(const float2*)(z + (size_t)rB * DIM + ks * 16 + 2 * cc + 8);
        split2(a0, ahi[ks * 4 + 0], alo[ks * 4 + 0]);
        split2(a1, ahi[ks * 4 + 1], alo[ks * 4 + 1]);
        split2(a2, ahi[ks * 4 + 2], alo[ks * 4 + 2]);
        split2(a3, ahi[ks * 4 + 3], alo[ks * 4 + 3]);
    }
    #pragma unroll
    for (int r4 = 0; r4 < 8; r4++) {
        g_afrag[((size_t)wt * 16 + r4) * 32 + lane] =
            make_uint4(ahi[r4*4], ahi[r4*4+1], ahi[r4*4+2], ahi[r4*4+3]);
        g_afrag[((size_t)wt * 16 + 8 + r4) * 32 + lane] =
            make_uint4(alo[r4*4], alo[r4*4+1], alo[r4*4+2], alo[r4*4+3]);
    }
    // per-row ||z||^2, sequential fp32 mul-then-add (reference rounding)
    if (lane < 16) {
        const float* zr = z + (size_t)(wt * 16 + lane) * DIM;
        float s = 0.f;
        for (int d = 0; d < DIM; d++)
            s = __fadd_rn(s, __fmul_rn(zr[d], zr[d]));
        g_zn[wt * 16 + lane] = s;
    }
}

// ---------------------------------------------------------------- argmin: persistent, work-stolen
// Tile = 64 rows x 256 codes. 2048 tiles, 444 CTAs (one wave at 3/SM).
// dot = zhi*ehi + zhi*elo + zlo*ehi (fp32 accum, chained into one C — full rate).
extern __shared__ char asm_smem[];

__global__ __launch_bounds__(128, 3) void argmin_mma() {
    __shared__ int s_tile;
    char* smem = asm_smem;
    const uint32_t sbase = smem_u32(smem);
    const int tid = threadIdx.x, wid = tid >> 5, lane = tid & 31;
    const int g = lane >> 2, cc = lane & 3;

    // ldmatrix per-lane row map: lanes 0-7 -> bh k0..7, 8-15 -> bh k8..15,
    // 16-23 -> bl k0..7, 24-31 -> bl k8..15 (matrix row = code n)
    const int sel = lane >> 3, r8 = lane & 7;
    const uint32_t laneoff = (uint32_t)((sel >> 1) * CHUNK_B + (sel & 1) * 16 + r8 * ROW_B);

    for (;;) {
        if (tid == 0) s_tile = (int)atomicAdd(&g_tilectr, 1u);
        __syncthreads();
        const int t = s_tile;
        if (t >= NTILES) break;
        const int rb = t >> 2;            // 64-row block
        const int code_base = (t & 3) * QCODES;
        const int wt = rb * 4 + wid;
        const int rA = wt * 16 + g, rB = rA + 8;

        // chunk 0 prefetch first (longest latency), then A fragments under it
        {
            uint32_t dst = sbase;
            const char* hs = (const char*)(g_ehi + (size_t)code_base * EPAD);
            const char* ls = (const char*)(g_elo + (size_t)code_base * EPAD);
            for (int i = tid; i < CHUNK_U4; i += 128) {
                cpasync16(dst + i * 16,           hs + i * 16);
                cpasync16(dst + CHUNK_B + i * 16, ls + i * 16);
            }
            CP_COMMIT();
        }

        uint32_t ahi[32], alo[32];
        #pragma unroll
        for (int r4 = 0; r4 < 8; r4++) {
            uint4 vh = g_afrag[((size_t)wt * 16 + r4) * 32 + lane];
            ahi[r4*4] = vh.x; ahi[r4*4+1] = vh.y; ahi[r4*4+2] = vh.z; ahi[r4*4+3] = vh.w;
            uint4 vl = g_afrag[((size_t)wt * 16 + 8 + r4) * 32 + lane];
            alo[r4*4] = vl.x; alo[r4*4+1] = vl.y; alo[r4*4+2] = vl.z; alo[r4*4+3] = vl.w;
        }
        const float znA = g_zn[rA];
        const float znB = g_zn[rB];

        CP_WAIT0();
        __syncthreads();

        float minvA = FLT_MAX, minvB = FLT_MAX;
        int   miniA = 0, miniB = 0;

        for (int c = 0; c < NCPT; c++) {
            if (c + 1 < NCPT) {
                uint32_t dst = sbase + ((c + 1) & 1) * BUF_B;
                const char* hs = (const char*)(g_ehi + (size_t)(code_base + (c + 1) * BN) * EPAD);
                const char* ls = (const char*)(g_elo + (size_t)(code_base + (c + 1) * BN) * EPAD);
                for (int i = tid; i < CHUNK_U4; i += 128) {
                    cpasync16(dst + i * 16,           hs + i * 16);
                    cpasync16(dst + CHUNK_B + i * 16, ls + i * 16);
                }
                CP_COMMIT();
            }

            const uint32_t bbase = sbase + (c & 1) * BUF_B + laneoff;
            const int cbase = code_base + c * BN;

            #pragma unroll
            for (int g2 = 0; g2 < 2; g2++) {
                float acc[4][4];
                #pragma unroll
                for (int q = 0; q < 4; q++)
                    #pragma unroll
                    for (int w = 0; w < 4; w++) acc[q][w] = 0.f;

                #pragma unroll
                for (int ks = 0; ks < 8; ks++) {
                    #pragma unroll
                    for (int ntl = 0; ntl < 4; ntl++) {
                        uint32_t b0, b1, b2, b3;
                        ldmatrix_x4(b0, b1, b2, b3,
                                    bbase + (g2 * 4 + ntl) * (8 * ROW_B) + ks * 32);
                        mma16816(acc[ntl], &ahi[ks * 4], b0, b1);   // hi*hi
                        mma16816(acc[ntl], &ahi[ks * 4], b2, b3);   // hi*lo
                        mma16816(acc[ntl], &alo[ks * 4], b0, b1);   // lo*hi
                    }
                }

                // q = (zn + en) + dot * (-2^-9)  [exact unscale, same rounding]
                float qA[8], qB[8];
                #pragma unroll
                for (int ntl = 0; ntl < 4; ntl++) {
                    int code0 = cbase + (g2 * 4 + ntl) * 8 + 2 * cc;
                    float2 en2 = *(const float2*)(g_enorm + code0);
                    qA[2*ntl]   = __fadd_rn(__fadd_rn(znA, en2.x), acc[ntl][0] * -0.001953125f);
                    qA[2*ntl+1] = __fadd_rn(__fadd_rn(znA, en2.y), acc[ntl][1] * -0.001953125f);
                    qB[2*ntl]   = __fadd_rn(__fadd_rn(znB, en2.x), acc[ntl][2] * -0.001953125f);
                    qB[2*ntl+1] = __fadd_rn(__fadd_rn(znB, en2.y), acc[ntl][3] * -0.001953125f);
                }
                float cmA = fminf(fminf(fminf(qA[0], qA[1]), fminf(qA[2], qA[3])),
                                  fminf(fminf(qA[4], qA[5]), fminf(qA[6], qA[7])));
                if (cmA < minvA) {
                    minvA = cmA;
                    #pragma unroll
                    for (int q = 7; q >= 0; q--)
                        if (qA[q] == cmA)
                            miniA = cbase + g2 * 32 + (q >> 1) * 8 + 2 * cc + (q & 1);
                }
                float cmB = fminf(fminf(fminf(qB[0], qB[1]), fminf(qB[2], qB[3])),
                                  fminf(fminf(qB[4], qB[5]), fminf(qB[6], qB[7])));
                if (cmB < minvB) {
                    minvB = cmB;
                    #pragma unroll
                    for (int q = 7; q >= 0; q--)
                        if (qB[q] == cmB)
                            miniB = cbase + g2 * 32 + (q >> 1) * 8 + 2 * cc + (q & 1);
                }
            }

            if (c + 1 < NCPT) CP_WAIT0();
            __syncthreads();
        }

        // lexicographic reduce across 4 lanes per row, then global atomicMin merge
        #pragma unroll
        for (int o = 1; o <= 2; o <<= 1) {
            float vA = __shfl_xor_sync(0xffffffffu, minvA, o);
            int   iA = __shfl_xor_sync(0xffffffffu, miniA, o);
            if (vA < minvA || (vA == minvA && iA < miniA)) { minvA = vA; miniA = iA; }
            float vB = __shfl_xor_sync(0xffffffffu, minvB, o);
            int   iB = __shfl_xor_sync(0xffffffffu, miniB, o);
            if (vB < minvB || (vB == minvB && iB < miniB)) { minvB = vB; miniB = iB; }
        }
        if (cc == 0) {
            atomicMin(&g_pack[rA], pack_vi(minvA, miniA));
            atomicMin(&g_pack[rB], pack_vi(minvB, miniB));
        }
    }
}

// ---------------------------------------------------------------- gather + loss + hist
__global__ void quantize_kernel(const float* __restrict__ z,
                                const float* __restrict__ emb,
                                const unsigned char* __restrict__ mask,
                                float* __restrict__ out) {
    const int warp = threadIdx.x >> 5;
    const int lane = threadIdx.x & 31;
    const int row  = blockIdx.x * QBLK + warp;
    const int code = (int)(g_pack[row] & 0xffffffffu);

    const float4 zv = *(const float4*)(z   + (size_t)row  * DIM + lane * 4);
    const float4 ev = *(const float4*)(emb + (size_t)code * DIM + lane * 4);

    float dx = __fadd_rn(ev.x, -zv.x);
    float dy = __fadd_rn(ev.y, -zv.y);
    float dz = __fadd_rn(ev.z, -zv.z);
    float dw = __fadd_rn(ev.w, -zv.w);

    float4 o;
    o.x = __fadd_rn(zv.x, dx);
    o.y = __fadd_rn(zv.y, dy);
    o.z = __fadd_rn(zv.z, dz);
    o.w = __fadd_rn(zv.w, dw);
    *(float4*)(out + (size_t)row * DIM + lane * 4) = o;

    float ss = dx * dx + dy * dy + dz * dz + dw * dw;
    #pragma unroll
    for (int off = 16; off; off >>= 1) ss += __shfl_xor_sync(0xffffffffu, ss, off);

    __shared__ float sps[QBLK];
    if (lane == 0) {
        sps[warp] = ss;
        if (!mask[row]) atomicAdd(&g_counts[code], 1);
    }
    __syncthreads();
    if (threadIdx.x == 0) {
        double b = 0.0;
        #pragma unroll
        for (int w = 0; w < QBLK; w++) b += (double)sps[w];
        g_losspart[blockIdx.x] = b;
    }
}

// ---------------------------------------------------------------- scalars
__global__ void finalize_kernel(const unsigned char* __restrict__ mask,
                                float* __restrict__ out, long long out_size) {
    __shared__ double dred[1024];
    __shared__ int    ired[1024];
    __shared__ float  fred[1024];
    const int k = threadIdx.x;

    int vsum = 0;
    {
        const uchar4* m4 = (const uchar4*)mask;
        #pragma unroll
        for (int i = 0; i < (N_TOK / 4) / 1024; i++) {
            uchar4 m = m4[k + i * 1024];
            vsum += (m.x ? 0 : 1) + (m.y ? 0 : 1) + (m.z ? 0 : 1) + (m.w ? 0 : 1);
        }
    }
    double lsum = 0.0;
    #pragma unroll
    for (int i = 0; i < NQB / 1024; i++) lsum += g_losspart[k + i * 1024];
    dred[k] = lsum;
    ired[k] = vsum;
    __syncthreads();
    for (int s = 512; s > 0; s >>= 1) {
        if (k < s) { dred[k] += dred[k + s]; ired[k] += ired[k + s]; }
        __syncthreads();
    }
    const float valid = (float)ired[0];
    const double losssum = dred[0];

    float p = __fdiv_rn((float)g_counts[k], valid);
    fred[k] = __fmul_rn(p, logf(__fadd_rn(p, 1e-10f)));
    __syncthreads();
    for (int s = 512; s > 0; s >>= 1) {
        if (k < s) fred[k] += fred[k + s];
        __syncthreads();
    }
    if (k == 0 && out_size >= (long long)N_TOK * DIM + 2) {
        double mean = losssum / (double)((long long)N_TOK * DIM);
        float v = (float)mean;
        out[(long long)N_TOK * DIM]     = __fadd_rn(v, __fmul_rn(0.25f, v));
        out[(long long)N_TOK * DIM + 1] = expf(-fred[0]);
    }
}

// ---------------------------------------------------------------- launch
extern "C" void kernel_launch(void* const* d_in, const int* in_sizes, int n_in,
                              void* d_out, int out_size) {
    const float* z = nullptr;
    const float* emb = nullptr;
    const unsigned char* mask = nullptr;
    for (int i = 0; i < n_in; i++) {
        if      (in_sizes[i] == N_TOK * DIM) z    = (const float*)d_in[i];
        else if (in_sizes[i] == KCODE * DIM) emb  = (const float*)d_in[i];
        else if (in_sizes[i] == N_TOK)       mask = (const unsigned char*)d_in[i];
    }
    float* out = (float*)d_out;

    cudaFuncSetAttribute(argmin_mma, cudaFuncAttributeMaxDynamicSharedMemorySize, SMEM_TOT);

    init_kernel    <<<34, 1024>>>();
    enorm_kernel   <<<4, 256>>>(emb);
    prep_e         <<<(KCODE * DIM) / 256, 256>>>(emb);
    prep_z         <<<NWT / 4, 128>>>(z);
    argmin_mma     <<<GRID_ARG, 128, SMEM_TOT>>>();
    quantize_kernel<<<NQB, QBLK * 32>>>(z, emb, mask, out);
    finalize_kernel<<<1, 1024>>>(mask, out, (long long)out_size);
}